// round 2
// baseline (speedup 1.0000x reference)
#include <cuda_runtime.h>
#include <cstdint>

// PlaneModel: B=8192, NV=8 (512 voxels), P=64, NS=32, HID1=16, BASE=32, OUT=13, D_IN=79
#define FULL 0xffffffffu
typedef unsigned long long u64;

__device__ __forceinline__ u64 dup2(float a){
    u64 r; asm("mov.b64 %0,{%1,%1};" : "=l"(r) : "f"(a)); return r;
}
__device__ __forceinline__ void upk2(u64 v, float& a, float& b){
    asm("mov.b64 {%0,%1},%2;" : "=f"(a), "=f"(b) : "l"(v));
}
__device__ __forceinline__ void fma2(u64& d, u64 a, u64 b){
    asm("fma.rn.f32x2 %0,%1,%2,%0;" : "+l"(d) : "l"(a), "l"(b));
}

__device__ __forceinline__ float wsum(float x){
    x += __shfl_xor_sync(FULL, x, 16);
    x += __shfl_xor_sync(FULL, x, 8);
    x += __shfl_xor_sync(FULL, x, 4);
    x += __shfl_xor_sync(FULL, x, 2);
    x += __shfl_xor_sync(FULL, x, 1);
    return x;
}

// single-batch accumulate: h[8] += x * w1row[0..15]
__device__ __forceinline__ void acc1(u64* h, float x, const float* wrow){
    u64 xx = dup2(x);
    const ulonglong2* w = (const ulonglong2*)wrow;
    #pragma unroll
    for (int t = 0; t < 4; t++){
        ulonglong2 wv = w[t];
        fma2(h[2*t],   xx, wv.x);
        fma2(h[2*t+1], xx, wv.y);
    }
}
// two-batch accumulate: one weight load, two batches' FMAs
__device__ __forceinline__ void acc2(u64* h0, u64* h1, float x0, float x1, const float* wrow){
    u64 a0 = dup2(x0), a1 = dup2(x1);
    const ulonglong2* w = (const ulonglong2*)wrow;
    #pragma unroll
    for (int t = 0; t < 4; t++){
        ulonglong2 wv = w[t];
        fma2(h0[2*t],   a0, wv.x);
        fma2(h0[2*t+1], a0, wv.y);
        fma2(h1[2*t],   a1, wv.x);
        fma2(h1[2*t+1], a1, wv.y);
    }
}

// pose features for batch b: rows 0..2 (picked xyz) and 67..78 (pos*e, R)
__device__ __forceinline__ void pose_acc(u64* h, int b, int idx, float e,
                                         const float* __restrict__ g_pos,
                                         const float* __restrict__ g_quat,
                                         const float* __restrict__ g_aabb,
                                         const float* __restrict__ s_w1)
{
    float qx = __ldg(g_quat + b*4 + 0), qy = __ldg(g_quat + b*4 + 1);
    float qz = __ldg(g_quat + b*4 + 2), qw = __ldg(g_quat + b*4 + 3);
    float rn = rsqrtf(qx*qx + qy*qy + qz*qz + qw*qw);
    qx *= rn; qy *= rn; qz *= rn; qw *= rn;
    float r00 = 1.f - 2.f*(qy*qy + qz*qz), r01 = 2.f*(qx*qy - qz*qw), r02 = 2.f*(qx*qz + qy*qw);
    float r10 = 2.f*(qx*qy + qz*qw), r11 = 1.f - 2.f*(qx*qx + qz*qz), r12 = 2.f*(qy*qz - qx*qw);
    float r20 = 2.f*(qx*qz - qy*qw), r21 = 2.f*(qy*qz + qx*qw), r22 = 1.f - 2.f*(qx*qx + qy*qy);

    float px = __ldg(g_pos + b*3 + 0), py = __ldg(g_pos + b*3 + 1), pz = __ldg(g_pos + b*3 + 2);
    float lox = __ldg(g_aabb + b*6 + 0), loy = __ldg(g_aabb + b*6 + 1), loz = __ldg(g_aabb + b*6 + 2);
    float hix = __ldg(g_aabb + b*6 + 3), hiy = __ldg(g_aabb + b*6 + 4), hiz = __ldg(g_aabb + b*6 + 5);

    // voxel center (meshgrid 'ij': n = i*64 + j*8 + k)
    float ci = (float)(idx >> 6)       + 0.5f;
    float cj = (float)((idx >> 3) & 7) + 0.5f;
    float ck = (float)(idx & 7)        + 0.5f;
    float vx = (ci * 0.125f) * (hix - lox) + lox;
    float vy = (cj * 0.125f) * (hiy - loy) + loy;
    float vz = (ck * 0.125f) * (hiz - loz) + loz;

    acc1(h, r00*vx + r01*vy + r02*vz + px, s_w1 + 0*16);
    acc1(h, r10*vx + r11*vy + r12*vz + py, s_w1 + 1*16);
    acc1(h, r20*vx + r21*vy + r22*vz + pz, s_w1 + 2*16);
    acc1(h, px*e, s_w1 + 67*16);
    acc1(h, py*e, s_w1 + 68*16);
    acc1(h, pz*e, s_w1 + 69*16);
    acc1(h, r00, s_w1 + 70*16);
    acc1(h, r01, s_w1 + 71*16);
    acc1(h, r02, s_w1 + 72*16);
    acc1(h, r10, s_w1 + 73*16);
    acc1(h, r11, s_w1 + 74*16);
    acc1(h, r12, s_w1 + 75*16);
    acc1(h, r20, s_w1 + 76*16);
    acc1(h, r21, s_w1 + 77*16);
    acc1(h, r22, s_w1 + 78*16);
}

// head MLP for one batch; v[16] = summed layer-1 features (identical on all lanes)
__device__ __forceinline__ void head(const float* v, int b, int lane,
                                     const float* __restrict__ g_w2a, const float* __restrict__ g_b2a,
                                     const float* __restrict__ g_g2a, const float* __restrict__ g_be2a,
                                     const float* __restrict__ g_w2b, const float* __restrict__ g_b2b,
                                     const float* __restrict__ g_g2b, const float* __restrict__ g_be2b,
                                     const float* __restrict__ g_wout,const float* __restrict__ g_bout,
                                     float* __restrict__ g_out)
{
    float a = __ldg(g_b2a + lane);
    #pragma unroll
    for (int i = 0; i < 16; i++) a = fmaf(v[i], __ldg(g_w2a + i*32 + lane), a);
    a = fmaxf(a, 0.f);
    float ma = wsum(a) * 0.03125f;
    float da = a - ma;
    float va = wsum(da*da) * 0.03125f;
    float ya = da * rsqrtf(va + 1e-6f) * __ldg(g_g2a + lane) + __ldg(g_be2a + lane);

    float c = __ldg(g_b2b + lane);
    #pragma unroll
    for (int i = 0; i < 32; i++)
        c = fmaf(__shfl_sync(FULL, ya, i), __ldg(g_w2b + i*32 + lane), c);
    c = fmaxf(c, 0.f);
    float mc = wsum(c) * 0.03125f;
    float dc = c - mc;
    float vc = wsum(dc*dc) * 0.03125f;
    float yb = dc * rsqrtf(vc + 1e-6f) * __ldg(g_g2b + lane) + __ldg(g_be2b + lane);
    float zf = yb + ya;   // residual

    float o = (lane < 13) ? __ldg(g_bout + lane) : 0.f;
    #pragma unroll
    for (int i = 0; i < 32; i++){
        float zi = __shfl_sync(FULL, zf, i);
        if (lane < 13) o = fmaf(zi, __ldg(g_wout + i*13 + lane), o);
    }
    if (lane < 13) g_out[b*13 + lane] = tanhf(o);
}

// relu + LN(16) per lane, x2, butterfly-sum over 32 samples -> v[16]
__device__ __forceinline__ void ln_reduce(u64* h, float* v,
                                          const float* s_g1, const float* s_be1)
{
    #pragma unroll
    for (int t = 0; t < 8; t++) upk2(h[t], v[2*t], v[2*t+1]);
    float m = 0.f;
    #pragma unroll
    for (int j = 0; j < 16; j++){ v[j] = fmaxf(v[j], 0.f); m += v[j]; }
    m *= 0.0625f;
    float var = 0.f;
    #pragma unroll
    for (int j = 0; j < 16; j++){ float d = v[j] - m; var += d*d; }
    var *= 0.0625f;
    float is = rsqrtf(var + 1e-6f);
    #pragma unroll
    for (int j = 0; j < 16; j++){
        float y = (v[j] - m) * is * s_g1[j] + s_be1[j];
        y += y;                                  // z = z + z
        y += __shfl_xor_sync(FULL, y, 16);
        y += __shfl_xor_sync(FULL, y, 8);
        y += __shfl_xor_sync(FULL, y, 4);
        y += __shfl_xor_sync(FULL, y, 2);
        y += __shfl_xor_sync(FULL, y, 1);
        v[j] = y;
    }
}

#define ZSTRIDE 36   // 32 cols + 4 pad: conflict-free STS.32 and LDS.128 readback

__global__ void __launch_bounds__(128, 4)
plane_kernel(const float* __restrict__ g_pos,  const float* __restrict__ g_quat,
             const float* __restrict__ g_xz,   const float* __restrict__ g_aabb,
             const int*   __restrict__ g_widx, const float* __restrict__ g_pls,
             const float* __restrict__ g_w1,   const float* __restrict__ g_b1,
             const float* __restrict__ g_g1,   const float* __restrict__ g_be1,
             const float* __restrict__ g_w2a,  const float* __restrict__ g_b2a,
             const float* __restrict__ g_g2a,  const float* __restrict__ g_be2a,
             const float* __restrict__ g_w2b,  const float* __restrict__ g_b2b,
             const float* __restrict__ g_g2b,  const float* __restrict__ g_be2b,
             const float* __restrict__ g_wout, const float* __restrict__ g_bout,
             float* __restrict__ g_out)
{
    __shared__ __align__(16) float s_w1[79*16];
    __shared__ __align__(16) float s_b1[16];
    __shared__ float s_g1[16], s_be1[16];
    __shared__ __align__(16) float s_z[4][2][32*ZSTRIDE];  // [warp][batch][row*ZSTRIDE+col]

    const int tid = threadIdx.x;
    for (int i = tid; i < 79*16; i += 128) s_w1[i] = g_w1[i];
    if (tid < 16){ s_b1[tid] = g_b1[tid]; s_g1[tid] = g_g1[tid]; s_be1[tid] = g_be1[tid]; }
    __syncthreads();

    const int warp = tid >> 5, lane = tid & 31;
    const int b0 = (blockIdx.x << 3) + (warp << 1);
    const int b1 = b0 + 1;
    float* sz0 = s_z[warp][0];
    float* sz1 = s_z[warp][1];

    const float e = expf(__ldg(g_pls));
    const int idx0 = __ldg(g_widx + b0*32 + lane);
    const int idx1 = __ldg(g_widx + b1*32 + lane);

    // init accumulators with bias, add pose rows (0-2, 67-78) per batch
    u64 h0[8], h1[8];
    #pragma unroll
    for (int t = 0; t < 8; t++){ h0[t] = *(const u64*)(s_b1 + 2*t); h1[t] = h0[t]; }
    pose_acc(h0, b0, idx0, e, g_pos, g_quat, g_aabb, s_w1);
    pose_acc(h1, b1, idx1, e, g_pos, g_quat, g_aabb, s_w1);

    const float* xzb0 = g_xz + ((size_t)b0 << 15);
    const float* xzb1 = g_xz + ((size_t)b1 << 15);

    // two k-phases: stage 32 cols of all 32 rows, then consume (rows 3..34, 35..66)
    #pragma unroll
    for (int ph = 0; ph < 2; ph++){
        const int coff = ph << 5;
        #pragma unroll
        for (int r = 0; r < 32; r++){
            int ir0 = __shfl_sync(FULL, idx0, r);
            int ir1 = __shfl_sync(FULL, idx1, r);
            sz0[r*ZSTRIDE + lane] = __ldg(xzb0 + (ir0 << 6) + coff + lane);
            sz1[r*ZSTRIDE + lane] = __ldg(xzb1 + (ir1 << 6) + coff + lane);
        }
        __syncwarp(FULL);
        const float* row0 = sz0 + lane*ZSTRIDE;
        const float* row1 = sz1 + lane*ZSTRIDE;
        const float* wbase = s_w1 + (3 + coff)*16;
        #pragma unroll
        for (int t = 0; t < 8; t++){
            float4 a = *(const float4*)(row0 + 4*t);
            float4 b = *(const float4*)(row1 + 4*t);
            acc2(h0, h1, a.x, b.x, wbase + (4*t + 0)*16);
            acc2(h0, h1, a.y, b.y, wbase + (4*t + 1)*16);
            acc2(h0, h1, a.z, b.z, wbase + (4*t + 2)*16);
            acc2(h0, h1, a.w, b.w, wbase + (4*t + 3)*16);
        }
        __syncwarp(FULL);
    }

    float v0[16], v1[16];
    ln_reduce(h0, v0, s_g1, s_be1);
    ln_reduce(h1, v1, s_g1, s_be1);

    head(v0, b0, lane, g_w2a, g_b2a, g_g2a, g_be2a, g_w2b, g_b2b, g_g2b, g_be2b, g_wout, g_bout, g_out);
    head(v1, b1, lane, g_w2a, g_b2a, g_g2a, g_be2a, g_w2b, g_b2b, g_g2b, g_be2b, g_wout, g_bout, g_out);
}

extern "C" void kernel_launch(void* const* d_in, const int* in_sizes, int n_in,
                              void* d_out, int out_size)
{
    (void)in_sizes; (void)n_in; (void)out_size;
    plane_kernel<<<1024, 128>>>(
        (const float*)d_in[0],  (const float*)d_in[1],  (const float*)d_in[2],
        (const float*)d_in[3],  (const int*)  d_in[4],  (const float*)d_in[5],
        (const float*)d_in[6],  (const float*)d_in[7],  (const float*)d_in[8],
        (const float*)d_in[9],  (const float*)d_in[10], (const float*)d_in[11],
        (const float*)d_in[12], (const float*)d_in[13], (const float*)d_in[14],
        (const float*)d_in[15], (const float*)d_in[16], (const float*)d_in[17],
        (const float*)d_in[18], (const float*)d_in[19],
        (float*)d_out);
}

// round 3
// speedup vs baseline: 1.5432x; 1.5432x over previous
#include <cuda_runtime.h>
#include <cstdint>

// PlaneModel: B=8192, NV=8 (512 voxels), P=64, NS=32, HID1=16, BASE=32, OUT=13, D_IN=79
#define FULL 0xffffffffu
typedef unsigned long long u64;

__device__ __forceinline__ u64 dup2(float a){
    u64 r; asm("mov.b64 %0,{%1,%1};" : "=l"(r) : "f"(a)); return r;
}
__device__ __forceinline__ void upk2(u64 v, float& a, float& b){
    asm("mov.b64 {%0,%1},%2;" : "=f"(a), "=f"(b) : "l"(v));
}
__device__ __forceinline__ void fma2(u64& d, u64 a, u64 b){
    asm("fma.rn.f32x2 %0,%1,%2,%0;" : "+l"(d) : "l"(a), "l"(b));
}

__device__ __forceinline__ float wsum(float x){
    x += __shfl_xor_sync(FULL, x, 16);
    x += __shfl_xor_sync(FULL, x, 8);
    x += __shfl_xor_sync(FULL, x, 4);
    x += __shfl_xor_sync(FULL, x, 2);
    x += __shfl_xor_sync(FULL, x, 1);
    return x;
}

// h[8] packed f32x2 accumulators += x * w1row[0..15]
__device__ __forceinline__ void acc1(u64* h, float x, const float* wrow){
    u64 xx = dup2(x);
    const ulonglong2* w = (const ulonglong2*)wrow;
    #pragma unroll
    for (int t = 0; t < 4; t++){
        ulonglong2 wv = w[t];
        fma2(h[2*t],   xx, wv.x);
        fma2(h[2*t+1], xx, wv.y);
    }
}

#define ZSTRIDE 68   // 32+32 cols + 4 pad: STS conflict-free; LDS.128 readback conflict-free

__global__ void __launch_bounds__(256, 3)
plane_kernel(const float* __restrict__ g_pos,  const float* __restrict__ g_quat,
             const float* __restrict__ g_xz,   const float* __restrict__ g_aabb,
             const int*   __restrict__ g_widx, const float* __restrict__ g_pls,
             const float* __restrict__ g_w1,   const float* __restrict__ g_b1,
             const float* __restrict__ g_g1,   const float* __restrict__ g_be1,
             const float* __restrict__ g_w2a,  const float* __restrict__ g_b2a,
             const float* __restrict__ g_g2a,  const float* __restrict__ g_be2a,
             const float* __restrict__ g_w2b,  const float* __restrict__ g_b2b,
             const float* __restrict__ g_g2b,  const float* __restrict__ g_be2b,
             const float* __restrict__ g_wout, const float* __restrict__ g_bout,
             float* __restrict__ g_out)
{
    extern __shared__ __align__(16) float smem[];
    float* s_w1  = smem;                 // 79*16 = 1264
    float* s_b1  = smem + 1264;          // 16
    float* s_g1  = smem + 1280;          // 16
    float* s_be1 = smem + 1296;          // 16
    float* s_z   = smem + 1312;          // 8 warps * 32*ZSTRIDE

    const int tid = threadIdx.x;
    for (int i = tid; i < 79*16; i += 256) s_w1[i] = g_w1[i];
    if (tid < 16){ s_b1[tid] = g_b1[tid]; s_g1[tid] = g_g1[tid]; s_be1[tid] = g_be1[tid]; }
    __syncthreads();

    const int warp = tid >> 5, lane = tid & 31;
    const int b = (blockIdx.x << 3) + warp;
    float* sz = s_z + warp * (32*ZSTRIDE);

    const int idx = __ldg(g_widx + b*32 + lane);

    // ---- stage all 64 columns of the 32 gathered rows (64 outstanding LDGs) ----
    const float* xzb = g_xz + ((size_t)b << 15);   // b * 512 * 64
    #pragma unroll
    for (int r = 0; r < 32; r++){
        int ir = __shfl_sync(FULL, idx, r);
        const float* src = xzb + (ir << 6);
        sz[r*ZSTRIDE + lane]      = __ldcs(src + lane);
        sz[r*ZSTRIDE + 32 + lane] = __ldcs(src + 32 + lane);
    }

    // ---- pose math overlaps the staging LDG latency ----
    float qx = __ldg(g_quat + b*4 + 0), qy = __ldg(g_quat + b*4 + 1);
    float qz = __ldg(g_quat + b*4 + 2), qw = __ldg(g_quat + b*4 + 3);
    float rn = rsqrtf(qx*qx + qy*qy + qz*qz + qw*qw);
    qx *= rn; qy *= rn; qz *= rn; qw *= rn;
    float r00 = 1.f - 2.f*(qy*qy + qz*qz), r01 = 2.f*(qx*qy - qz*qw), r02 = 2.f*(qx*qz + qy*qw);
    float r10 = 2.f*(qx*qy + qz*qw), r11 = 1.f - 2.f*(qx*qx + qz*qz), r12 = 2.f*(qy*qz - qx*qw);
    float r20 = 2.f*(qx*qz - qy*qw), r21 = 2.f*(qy*qz + qx*qw), r22 = 1.f - 2.f*(qx*qx + qy*qy);

    float px = __ldg(g_pos + b*3 + 0), py = __ldg(g_pos + b*3 + 1), pz = __ldg(g_pos + b*3 + 2);
    float lox = __ldg(g_aabb + b*6 + 0), loy = __ldg(g_aabb + b*6 + 1), loz = __ldg(g_aabb + b*6 + 2);
    float hix = __ldg(g_aabb + b*6 + 3), hiy = __ldg(g_aabb + b*6 + 4), hiz = __ldg(g_aabb + b*6 + 5);

    // voxel center (meshgrid 'ij': n = i*64 + j*8 + k)
    float ci = (float)(idx >> 6)       + 0.5f;
    float cj = (float)((idx >> 3) & 7) + 0.5f;
    float ck = (float)(idx & 7)        + 0.5f;
    float vx = (ci * 0.125f) * (hix - lox) + lox;
    float vy = (cj * 0.125f) * (hiy - loy) + loy;
    float vz = (ck * 0.125f) * (hiz - loz) + loz;
    float e = expf(__ldg(g_pls));

    u64 h[8];
    #pragma unroll
    for (int t = 0; t < 8; t++) h[t] = *(const u64*)(s_b1 + 2*t);

    acc1(h, r00*vx + r01*vy + r02*vz + px, s_w1 + 0*16);
    acc1(h, r10*vx + r11*vy + r12*vz + py, s_w1 + 1*16);
    acc1(h, r20*vx + r21*vy + r22*vz + pz, s_w1 + 2*16);
    acc1(h, px*e, s_w1 + 67*16);
    acc1(h, py*e, s_w1 + 68*16);
    acc1(h, pz*e, s_w1 + 69*16);
    acc1(h, r00, s_w1 + 70*16);
    acc1(h, r01, s_w1 + 71*16);
    acc1(h, r02, s_w1 + 72*16);
    acc1(h, r10, s_w1 + 73*16);
    acc1(h, r11, s_w1 + 74*16);
    acc1(h, r12, s_w1 + 75*16);
    acc1(h, r20, s_w1 + 76*16);
    acc1(h, r21, s_w1 + 77*16);
    acc1(h, r22, s_w1 + 78*16);

    __syncwarp(FULL);

    // ---- consume 64 xz features (rows 3..66) ----
    const float* row = sz + lane*ZSTRIDE;
    const float* wbase = s_w1 + 3*16;
    #pragma unroll
    for (int t = 0; t < 16; t++){
        float4 a = *(const float4*)(row + 4*t);
        acc1(h, a.x, wbase + (4*t + 0)*16);
        acc1(h, a.y, wbase + (4*t + 1)*16);
        acc1(h, a.z, wbase + (4*t + 2)*16);
        acc1(h, a.w, wbase + (4*t + 3)*16);
    }

    // ---- relu + LN(16) per lane, x2, butterfly-sum over the 32 samples ----
    float v[16];
    #pragma unroll
    for (int t = 0; t < 8; t++) upk2(h[t], v[2*t], v[2*t+1]);
    float m = 0.f;
    #pragma unroll
    for (int j = 0; j < 16; j++){ v[j] = fmaxf(v[j], 0.f); m += v[j]; }
    m *= 0.0625f;
    float var = 0.f;
    #pragma unroll
    for (int j = 0; j < 16; j++){ float d = v[j] - m; var += d*d; }
    var *= 0.0625f;
    float is = rsqrtf(var + 1e-6f);
    #pragma unroll
    for (int j = 0; j < 16; j++){
        float y = (v[j] - m) * is * s_g1[j] + s_be1[j];
        y += y;                                  // z = z + z
        y += __shfl_xor_sync(FULL, y, 16);
        y += __shfl_xor_sync(FULL, y, 8);
        y += __shfl_xor_sync(FULL, y, 4);
        y += __shfl_xor_sync(FULL, y, 2);
        y += __shfl_xor_sync(FULL, y, 1);
        v[j] = y;
    }

    // ---- head: lane = channel, 4-way split accumulators for short chains ----
    {
        float a0 = __ldg(g_b2a + lane), a1 = 0.f, a2 = 0.f, a3 = 0.f;
        #pragma unroll
        for (int i = 0; i < 16; i += 4){
            a0 = fmaf(v[i+0], __ldg(g_w2a + (i+0)*32 + lane), a0);
            a1 = fmaf(v[i+1], __ldg(g_w2a + (i+1)*32 + lane), a1);
            a2 = fmaf(v[i+2], __ldg(g_w2a + (i+2)*32 + lane), a2);
            a3 = fmaf(v[i+3], __ldg(g_w2a + (i+3)*32 + lane), a3);
        }
        float a = (a0 + a1) + (a2 + a3);
        a = fmaxf(a, 0.f);
        float ma = wsum(a) * 0.03125f;
        float da = a - ma;
        float va = wsum(da*da) * 0.03125f;
        float ya = da * rsqrtf(va + 1e-6f) * __ldg(g_g2a + lane) + __ldg(g_be2a + lane);

        float c0 = __ldg(g_b2b + lane), c1 = 0.f, c2 = 0.f, c3 = 0.f;
        #pragma unroll
        for (int i = 0; i < 32; i += 4){
            c0 = fmaf(__shfl_sync(FULL, ya, i+0), __ldg(g_w2b + (i+0)*32 + lane), c0);
            c1 = fmaf(__shfl_sync(FULL, ya, i+1), __ldg(g_w2b + (i+1)*32 + lane), c1);
            c2 = fmaf(__shfl_sync(FULL, ya, i+2), __ldg(g_w2b + (i+2)*32 + lane), c2);
            c3 = fmaf(__shfl_sync(FULL, ya, i+3), __ldg(g_w2b + (i+3)*32 + lane), c3);
        }
        float c = (c0 + c1) + (c2 + c3);
        c = fmaxf(c, 0.f);
        float mc = wsum(c) * 0.03125f;
        float dc = c - mc;
        float vc = wsum(dc*dc) * 0.03125f;
        float yb = dc * rsqrtf(vc + 1e-6f) * __ldg(g_g2b + lane) + __ldg(g_be2b + lane);
        float zf = yb + ya;   // residual

        float o0 = (lane < 13) ? __ldg(g_bout + lane) : 0.f;
        float o1 = 0.f;
        #pragma unroll
        for (int i = 0; i < 32; i += 2){
            float zi0 = __shfl_sync(FULL, zf, i);
            float zi1 = __shfl_sync(FULL, zf, i+1);
            if (lane < 13){
                o0 = fmaf(zi0, __ldg(g_wout + (i  )*13 + lane), o0);
                o1 = fmaf(zi1, __ldg(g_wout + (i+1)*13 + lane), o1);
            }
        }
        if (lane < 13) g_out[b*13 + lane] = tanhf(o0 + o1);
    }
}

extern "C" void kernel_launch(void* const* d_in, const int* in_sizes, int n_in,
                              void* d_out, int out_size)
{
    (void)in_sizes; (void)n_in; (void)out_size;
    const int SMEM_BYTES = (1312 + 8*32*ZSTRIDE) * 4;   // ~72.9 KB
    cudaFuncSetAttribute(plane_kernel,
                         cudaFuncAttributeMaxDynamicSharedMemorySize, SMEM_BYTES);
    plane_kernel<<<1024, 256, SMEM_BYTES>>>(
        (const float*)d_in[0],  (const float*)d_in[1],  (const float*)d_in[2],
        (const float*)d_in[3],  (const int*)  d_in[4],  (const float*)d_in[5],
        (const float*)d_in[6],  (const float*)d_in[7],  (const float*)d_in[8],
        (const float*)d_in[9],  (const float*)d_in[10], (const float*)d_in[11],
        (const float*)d_in[12], (const float*)d_in[13], (const float*)d_in[14],
        (const float*)d_in[15], (const float*)d_in[16], (const float*)d_in[17],
        (const float*)d_in[18], (const float*)d_in[19],
        (float*)d_out);
}